// round 1
// baseline (speedup 1.0000x reference)
#include <cuda_runtime.h>
#include <math_constants.h>

#define NROWS 262144
#define NC 100
#define POSCAP 4096
#define THRN 256
#define THRSTRIDE 257
#define K1_BLOCKS 2048
#define K1_THREADS 512
#define K1_ROWS_PER_WARP 8
#define K3_BLOCKS 296
#define K3_THREADS 512
#define K3_SMEM_BYTES ((NC*THRSTRIDE + NC)*4 + NC*4*3)

// ---------------- scratch (no allocations allowed) ----------------
__device__ float  g_lse[NROWS];
__device__ double g_ce_part[K1_BLOCKS];
__device__ int    g_pos_cnt[NC];
__device__ float  g_pos_buf[NC * POSCAP];
__device__ float  g_thr[NC * THRN];
__device__ float  g_tmax[NC];
__device__ float  g_wm[NC];
__device__ int    g_m[NC];
__device__ int    g_P[NC];
__device__ int    g_acc_int[NC];
__device__ int    g_acc_cnt[NC];

// ---------------- kernel 0: zero per-launch state ----------------
__global__ void k_init() {
    int i = threadIdx.x;
    if (i < NC) { g_pos_cnt[i] = 0; g_acc_int[i] = 0; g_acc_cnt[i] = 0; }
}

// ---------------- kernel 1: row pass (lse, CE, positive gather) ----------------
__global__ void __launch_bounds__(K1_THREADS) k1(const float* __restrict__ pred,
                                                 const int*   __restrict__ tgt,
                                                 const float* __restrict__ wt) {
    const float L2E = 1.4426950408889634f;
    const float LN2 = 0.6931471805599453f;
    int lane = threadIdx.x & 31;
    int wid  = threadIdx.x >> 5;
    int warpGlobal = blockIdx.x * (K1_THREADS / 32) + wid;

    float w0 = wt[lane], w1 = wt[lane + 32], w2 = wt[lane + 64];
    float w3 = (lane < 4) ? wt[lane + 96] : 0.f;

    // total weight sum (warp-uniform after butterfly)
    float W = w0 + w1 + w2 + w3;
    #pragma unroll
    for (int o = 16; o; o >>= 1) W += __shfl_xor_sync(0xffffffffu, W, o);

    double ce_local = 0.0;
    #pragma unroll 1
    for (int r = 0; r < K1_ROWS_PER_WARP; ++r) {
        int row = warpGlobal * K1_ROWS_PER_WARP + r;
        const float* p = pred + (size_t)row * NC;
        float x0 = p[lane], x1 = p[lane + 32], x2 = p[lane + 64];
        float x3 = (lane < 4) ? p[lane + 96] : -CUDART_INF_F;

        float mx = fmaxf(fmaxf(x0, x1), fmaxf(x2, x3));
        #pragma unroll
        for (int o = 16; o; o >>= 1) mx = fmaxf(mx, __shfl_xor_sync(0xffffffffu, mx, o));

        float e  = exp2f((x0 - mx) * L2E) + exp2f((x1 - mx) * L2E) + exp2f((x2 - mx) * L2E);
        float ws = w0 * x0 + w1 * x1 + w2 * x2;
        if (lane < 4) { e += exp2f((x3 - mx) * L2E); ws += w3 * x3; }

        int t = tgt[row];
        float xt = 0.f;
        if (lane == (t & 31)) {
            int jj = t >> 5;
            xt = (jj == 0) ? x0 : (jj == 1) ? x1 : (jj == 2) ? x2 : x3;
        }
        #pragma unroll
        for (int o = 16; o; o >>= 1) {
            e  += __shfl_xor_sync(0xffffffffu, e,  o);
            ws += __shfl_xor_sync(0xffffffffu, ws, o);
            xt += __shfl_xor_sync(0xffffffffu, xt, o);
        }
        float lse = mx + log2f(e) * LN2;

        if (lane == 0) {
            g_lse[row] = lse;
            int slot = atomicAdd(&g_pos_cnt[t], 1);
            g_pos_buf[t * POSCAP + slot] = xt - lse;       // own-class log-prob score
            float wt_t = __ldg(&wt[t]);
            float ce_row = -(0.9f * wt_t * (xt - lse) + 0.001f * (ws - lse * W));
            ce_local += (double)ce_row;
        }
    }

    __shared__ double sced[K1_THREADS / 32];
    if (lane == 0) sced[wid] = ce_local;
    __syncthreads();
    if (threadIdx.x == 0) {
        double s = 0.0;
        #pragma unroll
        for (int i = 0; i < K1_THREADS / 32; ++i) s += sced[i];
        g_ce_part[blockIdx.x] = s;
    }
}

// ---------------- kernel 2: per-class sort of positives + thresholds ----------------
__global__ void __launch_bounds__(512) k2() {
    __shared__ float sb[POSCAP];
    int c = blockIdx.x, tid = threadIdx.x;
    int P = g_pos_cnt[c];
    for (int i = tid; i < POSCAP; i += 512)
        sb[i] = (i < P) ? g_pos_buf[c * POSCAP + i] : CUDART_INF_F;
    __syncthreads();

    for (int k = 2; k <= POSCAP; k <<= 1) {
        for (int j = k >> 1; j > 0; j >>= 1) {
            for (int i = tid; i < POSCAP; i += 512) {
                int ixj = i ^ j;
                if (ixj > i) {
                    float a = sb[i], b = sb[ixj];
                    bool up = ((i & k) == 0);
                    if ((a > b) == up) { sb[i] = b; sb[ixj] = a; }
                }
            }
            __syncthreads();
        }
    }

    double a  = 0.95 * (double)P;
    int    K0 = (int)floor(a) + 1;
    int    m  = P - K0 + 1;
    if (m < 0) m = 0;
    if (m > THRN) m = THRN;

    if (tid < THRN) g_thr[c * THRN + tid] = (tid < m) ? sb[tid] : CUDART_INF_F;
    if (tid == 0) {
        g_m[c] = m; g_P[c] = P;
        g_wm[c] = (float)((double)K0 - a);
        g_tmax[c] = (m > 0) ? sb[m - 1] : -CUDART_INF_F;
    }
}

// ---------------- kernel 3: counting pass over all (sample, class) pairs ----------------
__global__ void __launch_bounds__(K3_THREADS) k3(const float* __restrict__ pred,
                                                 const int*   __restrict__ tgt) {
    extern __shared__ unsigned char dynraw[];
    float* sthr  = (float*)dynraw;                   // NC * THRSTRIDE (bank-safe stride)
    float* stmax = sthr + NC * THRSTRIDE;            // NC
    int*   sm_   = (int*)(stmax + NC);               // NC
    int*   sacc  = sm_ + NC;                         // NC
    int*   scnt  = sacc + NC;                        // NC

    int tid = threadIdx.x;
    for (int i = tid; i < NC * THRN; i += K3_THREADS) {
        int c = i >> 8, j = i & 255;
        sthr[c * THRSTRIDE + j] = g_thr[i];
    }
    for (int i = tid; i < NC; i += K3_THREADS) {
        stmax[i] = g_tmax[i]; sm_[i] = g_m[i]; sacc[i] = 0; scnt[i] = 0;
    }
    __syncthreads();

    int lane = tid & 31, wid = tid >> 5;
    int warpGlobal = blockIdx.x * (K3_THREADS / 32) + wid;
    const int totalWarps = K3_BLOCKS * (K3_THREADS / 32);

    for (int row = warpGlobal; row < NROWS; row += totalWarps) {
        const float* p = pred + (size_t)row * NC;
        float lse = g_lse[row];
        int   t   = tgt[row];
        #pragma unroll
        for (int jj = 0; jj < 4; ++jj) {
            int  c  = lane + jj * 32;
            bool in = (jj < 3) | (lane < 4);
            float s = 0.f;
            bool act = false;
            if (in) {
                s   = p[c] - lse;
                act = (c != t) & (s < stmax[c]);    // ~5% of pairs pass
            }
            if (__ballot_sync(0xffffffffu, act)) {
                if (act) {
                    int b = 0, base = c * THRSTRIDE;
                    #pragma unroll
                    for (int st = 128; st; st >>= 1) {
                        int t2 = b + st;
                        if (sthr[base + t2 - 1] <= s) b = t2;
                    }
                    atomicAdd(&sacc[c], sm_[c] - 1 - b);   // exact integer accumulation
                    atomicAdd(&scnt[c], 1);
                }
            }
        }
    }
    __syncthreads();
    for (int i = tid; i < NC; i += K3_THREADS) {
        atomicAdd(&g_acc_int[i], sacc[i]);
        atomicAdd(&g_acc_cnt[i], scnt[i]);
    }
}

// ---------------- kernel 4: final scalar combine ----------------
__global__ void __launch_bounds__(256) k4(const float* __restrict__ wt, float* __restrict__ out) {
    __shared__ double sd[256];
    int tid = threadIdx.x;

    double s = 0.0;
    for (int i = tid; i < K1_BLOCKS; i += 256) s += g_ce_part[i];
    sd[tid] = s; __syncthreads();
    for (int o = 128; o; o >>= 1) { if (tid < o) sd[tid] += sd[tid + o]; __syncthreads(); }
    double ce = sd[0] / (double)NROWS;
    __syncthreads();

    double pw = 0.0, wsum = 0.0;
    for (int c = tid; c < NC; c += 256) {
        int P = g_P[c], m = g_m[c];
        double pauc = 0.0;
        if (P > 0 && m > 0) {
            double Nn = (double)(NROWS - P);
            pauc = ((double)g_acc_int[c] + (double)g_wm[c] * (double)g_acc_cnt[c])
                   / (Nn * (double)P);
        }
        double w = (double)wt[c];
        pw += pauc * w;
        wsum += w;
    }
    sd[tid] = pw; __syncthreads();
    for (int o = 128; o; o >>= 1) { if (tid < o) sd[tid] += sd[tid + o]; __syncthreads(); }
    double pwt = sd[0]; __syncthreads();
    sd[tid] = wsum; __syncthreads();
    for (int o = 128; o; o >>= 1) { if (tid < o) sd[tid] += sd[tid + o]; __syncthreads(); }
    double wst = sd[0];

    if (tid == 0) {
        double avg = pwt / (wst * 0.05);
        avg = fmin(fmax(avg, 0.0), 1.0);
        double loss = 0.5 * ce + 0.5 * (1.0 - avg * avg);
        out[0] = (float)loss;
    }
}

// ---------------- launch ----------------
extern "C" void kernel_launch(void* const* d_in, const int* in_sizes, int n_in,
                              void* d_out, int out_size) {
    const float* pred = (const float*)d_in[0];
    const int*   tgt  = (const int*)d_in[1];
    const float* wt   = (const float*)d_in[2];
    float*       out  = (float*)d_out;

    cudaFuncSetAttribute(k3, cudaFuncAttributeMaxDynamicSharedMemorySize, K3_SMEM_BYTES);

    k_init<<<1, 128>>>();
    k1<<<K1_BLOCKS, K1_THREADS>>>(pred, tgt, wt);
    k2<<<NC, 512>>>();
    k3<<<K3_BLOCKS, K3_THREADS, K3_SMEM_BYTES>>>(pred, tgt);
    k4<<<1, 256>>>(wt, out);
}

// round 2
// speedup vs baseline: 1.2689x; 1.2689x over previous
#include <cuda_runtime.h>
#include <math_constants.h>

#define NROWS 262144
#define NC 100
#define POSCAP 4096
#define THRN 192
#define THRSTRIDE 193
#define K1_BLOCKS 2048
#define K1_THREADS 512
#define K1_RPW 8
#define K3_BLOCKS 296
#define K3_THREADS 512
#define K3_WARPS (K3_THREADS/32)
#define QCAP 136

// smem layout offsets for k3 (bytes)
#define OFF_STHR   0
#define OFF_STMX   (OFF_STHR + NC*THRSTRIDE*4)          // 77200
#define OFF_QS     (OFF_STMX + NC*4)                    // 77600
#define OFF_QC     (OFF_QS + K3_WARPS*QCAP*4)           // 86304
#define OFF_SM     (OFF_QC + K3_WARPS*QCAP*4)           // 95008
#define OFF_ACC64  (OFF_SM + NC*4)                      // 95408 (8-aligned)
#define K3_SMEM_BYTES (OFF_ACC64 + NC*8)                // 96208

// ---------------- scratch ----------------
__device__ float  g_lse[NROWS];
__device__ double g_ce_part[K1_BLOCKS];
__device__ int    g_pos_cnt[NC];
__device__ float  g_pos_buf[NC * POSCAP];
__device__ float  g_thr[NC * THRN];
__device__ float  g_tmax[NC];
__device__ float  g_wm[NC];
__device__ int    g_m[NC];
__device__ int    g_P[NC];
__device__ unsigned long long g_acc[NC];

__device__ __forceinline__ float ex2f(float x) {
    float y; asm("ex2.approx.f32 %0, %1;" : "=f"(y) : "f"(x)); return y;
}
__device__ __forceinline__ float lg2f(float x) {
    float y; asm("lg2.approx.f32 %0, %1;" : "=f"(y) : "f"(x)); return y;
}

// ---------------- kernel 0 ----------------
__global__ void k_init() {
    int i = threadIdx.x;
    if (i < NC) { g_pos_cnt[i] = 0; g_acc[i] = 0ULL; }
}

// ---------------- kernel 1: row pass ----------------
__global__ void __launch_bounds__(K1_THREADS) k1(const float* __restrict__ pred,
                                                 const int*   __restrict__ tgt,
                                                 const float* __restrict__ wt) {
    const float L2E = 1.4426950408889634f;
    const float LN2 = 0.6931471805599453f;
    int lane = threadIdx.x & 31;
    int wid  = threadIdx.x >> 5;
    int warpGlobal = blockIdx.x * (K1_THREADS / 32) + wid;

    float4 wv = make_float4(0.f, 0.f, 0.f, 0.f);
    if (lane < 25) wv = ((const float4*)wt)[lane];
    float W = wv.x + wv.y + wv.z + wv.w;
    #pragma unroll
    for (int o = 16; o; o >>= 1) W += __shfl_xor_sync(0xffffffffu, W, o);

    double ce_local = 0.0;
    int row0 = warpGlobal * K1_RPW;

    // prefetch first row
    float4 v = make_float4(0.f, 0.f, 0.f, 0.f);
    if (lane < 25) v = __ldg((const float4*)(pred + (size_t)row0 * NC) + lane);
    int tl = (lane == 25) ? __ldg(&tgt[row0]) : 0;
    int t  = __shfl_sync(0xffffffffu, tl, 25);

    #pragma unroll 1
    for (int r = 0; r < K1_RPW; ++r) {
        int row = row0 + r;
        float4 vn = make_float4(0.f, 0.f, 0.f, 0.f);
        int tn = 0;
        if (r + 1 < K1_RPW) {
            if (lane < 25) vn = __ldg((const float4*)(pred + (size_t)(row + 1) * NC) + lane);
            int tln = (lane == 25) ? __ldg(&tgt[row + 1]) : 0;
            tn = __shfl_sync(0xffffffffu, tln, 25);
        }

        float m4 = (lane < 25) ? fmaxf(fmaxf(v.x, v.y), fmaxf(v.z, v.w)) : -CUDART_INF_F;
        #pragma unroll
        for (int o = 16; o; o >>= 1) m4 = fmaxf(m4, __shfl_xor_sync(0xffffffffu, m4, o));
        float mx = m4;

        float e = 0.f, ws = 0.f;
        if (lane < 25) {
            e = ex2f((v.x - mx) * L2E) + ex2f((v.y - mx) * L2E)
              + ex2f((v.z - mx) * L2E) + ex2f((v.w - mx) * L2E);
            ws = wv.x * v.x + wv.y * v.y + wv.z * v.z + wv.w * v.w;
        }

        int slot = t & 3, owner = t >> 2;
        float xo = (slot == 0) ? v.x : (slot == 1) ? v.y : (slot == 2) ? v.z : v.w;
        float xt = __shfl_sync(0xffffffffu, xo, owner);

        #pragma unroll
        for (int o = 16; o; o >>= 1) {
            e  += __shfl_xor_sync(0xffffffffu, e,  o);
            ws += __shfl_xor_sync(0xffffffffu, ws, o);
        }
        float lse = mx + lg2f(e) * LN2;

        if (lane == 0) {
            g_lse[row] = lse;
            int sl = atomicAdd(&g_pos_cnt[t], 1);
            g_pos_buf[t * POSCAP + sl] = xt - lse;
            float wtt = __ldg(&wt[t]);
            ce_local += (double)(-(0.9f * wtt * (xt - lse) + 0.001f * (ws - lse * W)));
        }
        v = vn; t = tn;
    }

    __shared__ double sced[K1_THREADS / 32];
    if (lane == 0) sced[wid] = ce_local;
    __syncthreads();
    if (threadIdx.x == 0) {
        double s = 0.0;
        #pragma unroll
        for (int i = 0; i < K1_THREADS / 32; ++i) s += sced[i];
        g_ce_part[blockIdx.x] = s;
    }
}

// ---------------- kernel 2: per-class sort + thresholds ----------------
__global__ void __launch_bounds__(512) k2() {
    __shared__ float sb[POSCAP];
    int c = blockIdx.x, tid = threadIdx.x;
    int P = g_pos_cnt[c];
    for (int i = tid; i < POSCAP; i += 512)
        sb[i] = (i < P) ? g_pos_buf[c * POSCAP + i] : CUDART_INF_F;
    __syncthreads();

    for (int k = 2; k <= POSCAP; k <<= 1) {
        for (int j = k >> 1; j > 0; j >>= 1) {
            for (int i = tid; i < POSCAP; i += 512) {
                int ixj = i ^ j;
                if (ixj > i) {
                    float a = sb[i], b = sb[ixj];
                    bool up = ((i & k) == 0);
                    if ((a > b) == up) { sb[i] = b; sb[ixj] = a; }
                }
            }
            __syncthreads();
        }
    }

    double a  = 0.95 * (double)P;
    int    K0 = (int)floor(a) + 1;
    int    m  = P - K0 + 1;
    if (m < 0) m = 0;
    if (m > THRN) m = THRN;

    if (tid < THRN) g_thr[c * THRN + tid] = (tid < m) ? sb[tid] : CUDART_INF_F;
    if (tid == 0) {
        g_m[c] = m; g_P[c] = P;
        g_wm[c] = (float)((double)K0 - a);
        g_tmax[c] = (m > 0) ? sb[m - 1] : -CUDART_INF_F;
    }
}

// ---------------- kernel 3: counting pass with warp compaction ----------------
__global__ void __launch_bounds__(K3_THREADS) k3(const float* __restrict__ pred,
                                                 const int*   __restrict__ tgt) {
    extern __shared__ unsigned char raw[];
    float* sthr = (float*)(raw + OFF_STHR);
    float* stmx = (float*)(raw + OFF_STMX);
    float* qsb  = (float*)(raw + OFF_QS);
    int*   qcb  = (int*)  (raw + OFF_QC);
    int*   sm_  = (int*)  (raw + OFF_SM);
    unsigned long long* acc64 = (unsigned long long*)(raw + OFF_ACC64);

    int tid = threadIdx.x;
    for (int i = tid; i < NC * THRN; i += K3_THREADS) {
        int c = i / THRN, j = i - c * THRN;
        sthr[c * THRSTRIDE + j] = g_thr[i];
    }
    for (int i = tid; i < NC; i += K3_THREADS) {
        stmx[i] = g_tmax[i]; sm_[i] = g_m[i]; acc64[i] = 0ULL;
    }
    __syncthreads();

    int lane = tid & 31, wid = tid >> 5;
    int*   myqc = qcb + wid * QCAP;
    float* myqs = qsb + wid * QCAP;

    float tm0 = -CUDART_INF_F, tm1 = -CUDART_INF_F, tm2 = -CUDART_INF_F, tm3 = -CUDART_INF_F;
    if (lane < 25) {
        tm0 = stmx[4 * lane]; tm1 = stmx[4 * lane + 1];
        tm2 = stmx[4 * lane + 2]; tm3 = stmx[4 * lane + 3];
    }

    int qn = 0;
    int warpGlobal = blockIdx.x * K3_WARPS + wid;
    const int stride = K3_BLOCKS * K3_WARPS;

    for (int row = warpGlobal; row < NROWS; row += stride) {
        float4 v = make_float4(0.f, 0.f, 0.f, 0.f);
        if (lane < 25) v = __ldg((const float4*)(pred + (size_t)row * NC) + lane);
        float lsel = (lane == 25) ? g_lse[row] : 0.f;
        int   tl   = (lane == 26) ? __ldg(&tgt[row]) : 0;
        float lse = __shfl_sync(0xffffffffu, lsel, 25);
        int   t   = __shfl_sync(0xffffffffu, tl, 26);

        int mask = 0;
        float s0 = 0.f, s1 = 0.f, s2 = 0.f, s3 = 0.f;
        if (lane < 25) {
            s0 = v.x - lse; s1 = v.y - lse; s2 = v.z - lse; s3 = v.w - lse;
            int c0 = 4 * lane;
            mask  = ((s0 < tm0) & (c0     != t)) ? 1 : 0;
            mask |= ((s1 < tm1) & (c0 + 1 != t)) ? 2 : 0;
            mask |= ((s2 < tm2) & (c0 + 2 != t)) ? 4 : 0;
            mask |= ((s3 < tm3) & (c0 + 3 != t)) ? 8 : 0;
        }
        int cnt = __popc(mask);
        int inc = cnt;
        #pragma unroll
        for (int o = 1; o < 32; o <<= 1) {
            int n = __shfl_up_sync(0xffffffffu, inc, o);
            if (lane >= o) inc += n;
        }
        int tot = __shfl_sync(0xffffffffu, inc, 31);
        if (tot) {
            int base = qn + inc - cnt;
            while (mask) {
                int k = __ffs(mask) - 1; mask &= mask - 1;
                float sv = (k == 0) ? s0 : (k == 1) ? s1 : (k == 2) ? s2 : s3;
                myqc[base] = 4 * lane + k;
                myqs[base] = sv;
                base++;
            }
            qn += tot;
            __syncwarp();
            while (qn >= 32) {
                qn -= 32;
                int c = myqc[qn + lane];
                float s = myqs[qn + lane];
                int b = 0, tb = c * THRSTRIDE;
                #pragma unroll
                for (int st = 128; st; st >>= 1)
                    if (sthr[tb + b + st - 1] <= s) b += st;
                unsigned long long up = (1ULL << 32) | (unsigned int)(sm_[c] - 1 - b);
                atomicAdd(&acc64[c], up);
            }
            __syncwarp();
        }
    }
    // drain leftovers (< 32)
    __syncwarp();
    if (lane < qn) {
        int c = myqc[lane];
        float s = myqs[lane];
        int b = 0, tb = c * THRSTRIDE;
        #pragma unroll
        for (int st = 128; st; st >>= 1)
            if (sthr[tb + b + st - 1] <= s) b += st;
        unsigned long long up = (1ULL << 32) | (unsigned int)(sm_[c] - 1 - b);
        atomicAdd(&acc64[c], up);
    }
    __syncthreads();
    for (int i = tid; i < NC; i += K3_THREADS) {
        unsigned long long v = acc64[i];
        if (v) atomicAdd(&g_acc[i], v);
    }
}

// ---------------- kernel 4: final combine ----------------
__global__ void __launch_bounds__(256) k4(const float* __restrict__ wt, float* __restrict__ out) {
    __shared__ double sd[256];
    int tid = threadIdx.x;

    double s = 0.0;
    for (int i = tid; i < K1_BLOCKS; i += 256) s += g_ce_part[i];
    sd[tid] = s; __syncthreads();
    for (int o = 128; o; o >>= 1) { if (tid < o) sd[tid] += sd[tid + o]; __syncthreads(); }
    double ce = sd[0] / (double)NROWS;
    __syncthreads();

    double pw = 0.0, wsum = 0.0;
    for (int c = tid; c < NC; c += 256) {
        int P = g_P[c], m = g_m[c];
        double pauc = 0.0;
        if (P > 0 && m > 0) {
            unsigned long long a = g_acc[c];
            double isum = (double)(unsigned int)(a & 0xffffffffULL);
            double icnt = (double)(unsigned int)(a >> 32);
            double Nn = (double)(NROWS - P);
            pauc = (isum + (double)g_wm[c] * icnt) / (Nn * (double)P);
        }
        double w = (double)wt[c];
        pw += pauc * w;
        wsum += w;
    }
    sd[tid] = pw; __syncthreads();
    for (int o = 128; o; o >>= 1) { if (tid < o) sd[tid] += sd[tid + o]; __syncthreads(); }
    double pwt = sd[0]; __syncthreads();
    sd[tid] = wsum; __syncthreads();
    for (int o = 128; o; o >>= 1) { if (tid < o) sd[tid] += sd[tid + o]; __syncthreads(); }
    double wst = sd[0];

    if (tid == 0) {
        double avg = pwt / (wst * 0.05);
        avg = fmin(fmax(avg, 0.0), 1.0);
        out[0] = (float)(0.5 * ce + 0.5 * (1.0 - avg * avg));
    }
}

// ---------------- launch ----------------
extern "C" void kernel_launch(void* const* d_in, const int* in_sizes, int n_in,
                              void* d_out, int out_size) {
    const float* pred = (const float*)d_in[0];
    const int*   tgt  = (const int*)d_in[1];
    const float* wt   = (const float*)d_in[2];
    float*       out  = (float*)d_out;

    cudaFuncSetAttribute(k3, cudaFuncAttributeMaxDynamicSharedMemorySize, K3_SMEM_BYTES);

    k_init<<<1, 128>>>();
    k1<<<K1_BLOCKS, K1_THREADS>>>(pred, tgt, wt);
    k2<<<NC, 512>>>();
    k3<<<K3_BLOCKS, K3_THREADS, K3_SMEM_BYTES>>>(pred, tgt);
    k4<<<1, 256>>>(wt, out);
}

// round 8
// speedup vs baseline: 1.3680x; 1.0781x over previous
#include <cuda_runtime.h>
#include <math_constants.h>

#define NROWS 262144
#define NC 100
#define POSCAP 4096
#define THRN 192
#define THRSTRIDE 193
#define K1_BLOCKS 1024
#define K1_THREADS 512
#define K1_RPW 16
#define K3_BLOCKS 296
#define K3_THREADS 1024
#define K3_WARPS (K3_THREADS/32)
#define QCAP 136

// k3 smem layout (bytes)
#define OFF_STHR   0
#define OFF_STMX   (OFF_STHR + NC*THRSTRIDE*4)            // 77200
#define OFF_SM     (OFF_STMX + NC*4)                      // 77600
#define OFF_ACC64  (OFF_SM + NC*4)                        // 78000 -> pad to 8
#define OFF_Q      (OFF_ACC64 + NC*8)                     // 78800
#define K3_SMEM_BYTES (OFF_Q + K3_WARPS*QCAP*8)           // 113616

// ---------------- scratch ----------------
__device__ float  g_lse[NROWS];
__device__ double g_ce_part[K1_BLOCKS];
__device__ int    g_pos_cnt[NC];
__device__ float  g_pos_buf[NC * POSCAP];
__device__ float  g_thr[NC * THRN];
__device__ float  g_tmax[NC];
__device__ float  g_wm[NC];
__device__ int    g_m[NC];
__device__ int    g_P[NC];
__device__ unsigned long long g_acc[NC];

__device__ __forceinline__ float ex2f(float x) {
    float y; asm("ex2.approx.f32 %0, %1;" : "=f"(y) : "f"(x)); return y;
}
__device__ __forceinline__ float lg2f(float x) {
    float y; asm("lg2.approx.f32 %0, %1;" : "=f"(y) : "f"(x)); return y;
}

// ---------------- kernel 0 ----------------
__global__ void k_init() {
    int i = threadIdx.x;
    if (i < NC) { g_pos_cnt[i] = 0; g_acc[i] = 0ULL; }
}

// ---------------- kernel 1: row pass (no max chain, 4-row ILP) ----------------
__global__ void __launch_bounds__(K1_THREADS) k1(const float* __restrict__ pred,
                                                 const int*   __restrict__ tgt,
                                                 const float* __restrict__ wt) {
    const float L2E = 1.4426950408889634f;
    const float LN2 = 0.6931471805599453f;
    const unsigned FULL = 0xffffffffu;
    int lane = threadIdx.x & 31;
    int wid  = threadIdx.x >> 5;
    int warpGlobal = blockIdx.x * (K1_THREADS / 32) + wid;
    int row0 = warpGlobal * K1_RPW;

    float4 wv = make_float4(0.f, 0.f, 0.f, 0.f);
    if (lane < 25) wv = __ldg((const float4*)wt + lane);
    float W = wv.x + wv.y + wv.z + wv.w;
    #pragma unroll
    for (int o = 16; o; o >>= 1) W += __shfl_xor_sync(FULL, W, o);

    int tA = (lane < K1_RPW) ? __ldg(&tgt[row0 + lane]) : 0;

    float  ps  = 0.f;      // per-thread  sum of w_j * x_j
    double ce0 = 0.0;      // lane0 per-row terms

    #pragma unroll 1
    for (int it = 0; it < K1_RPW / 4; ++it) {
        float4 v[4];
        float  e[4];
        int    t[4];
        #pragma unroll
        for (int k = 0; k < 4; ++k) {
            int row = row0 + it * 4 + k;
            v[k] = make_float4(0.f, 0.f, 0.f, 0.f);
            if (lane < 25) v[k] = __ldg((const float4*)(pred + (size_t)row * NC) + lane);
            t[k] = __shfl_sync(FULL, tA, it * 4 + k);
        }
        #pragma unroll
        for (int k = 0; k < 4; ++k) {
            e[k] = 0.f;
            if (lane < 25) {
                e[k] = ex2f(v[k].x * L2E) + ex2f(v[k].y * L2E)
                     + ex2f(v[k].z * L2E) + ex2f(v[k].w * L2E);
                ps  += wv.x * v[k].x + wv.y * v[k].y + wv.z * v[k].z + wv.w * v[k].w;
            }
        }
        #pragma unroll
        for (int o = 16; o; o >>= 1) {
            #pragma unroll
            for (int k = 0; k < 4; ++k) e[k] += __shfl_xor_sync(FULL, e[k], o);
        }
        #pragma unroll
        for (int k = 0; k < 4; ++k) {
            float lse = lg2f(e[k]) * LN2;
            int   tk  = t[k];
            int   sl4 = tk & 3;
            float xo  = (sl4 == 0) ? v[k].x : (sl4 == 1) ? v[k].y : (sl4 == 2) ? v[k].z : v[k].w;
            float xt  = __shfl_sync(FULL, xo, tk >> 2);
            if (lane == 0) {
                int row = row0 + it * 4 + k;
                g_lse[row] = lse;
                int sl = atomicAdd(&g_pos_cnt[tk], 1);
                if (sl < POSCAP) g_pos_buf[tk * POSCAP + sl] = xt - lse;
                float wtt = __ldg(&wt[tk]);
                ce0 += (double)(0.9f * wtt * (lse - xt) + 0.001f * W * lse);
            }
        }
    }

    // warp-reduce ps, then block combine
    #pragma unroll
    for (int o = 16; o; o >>= 1) ps += __shfl_xor_sync(FULL, ps, o);

    __shared__ double sced[K1_THREADS / 32];
    __shared__ float  sps[K1_THREADS / 32];
    if (lane == 0) { sced[wid] = ce0; sps[wid] = ps; }
    __syncthreads();
    if (threadIdx.x == 0) {
        double sc = 0.0, sp = 0.0;
        #pragma unroll
        for (int i = 0; i < K1_THREADS / 32; ++i) { sc += sced[i]; sp += (double)sps[i]; }
        g_ce_part[blockIdx.x] = sc - 0.001 * sp;
    }
}

// ---------------- kernel 2: per-class sort + thresholds ----------------
__global__ void __launch_bounds__(1024) k2() {
    __shared__ float sb[POSCAP];
    int c = blockIdx.x, tid = threadIdx.x;
    int P = g_pos_cnt[c];
    if (P > POSCAP) P = POSCAP;
    for (int i = tid; i < POSCAP; i += 1024)
        sb[i] = (i < P) ? g_pos_buf[c * POSCAP + i] : CUDART_INF_F;
    __syncthreads();

    for (int k = 2; k <= POSCAP; k <<= 1) {
        for (int j = k >> 1; j > 0; j >>= 1) {
            for (int i = tid; i < POSCAP; i += 1024) {
                int ixj = i ^ j;
                if (ixj > i) {
                    float a = sb[i], b = sb[ixj];
                    bool up = ((i & k) == 0);
                    if ((a > b) == up) { sb[i] = b; sb[ixj] = a; }
                }
            }
            __syncthreads();
        }
    }

    double a  = 0.95 * (double)P;
    int    K0 = (int)floor(a) + 1;
    int    m  = P - K0 + 1;
    if (m < 0) m = 0;
    if (m > THRN) m = THRN;

    if (tid < THRN) g_thr[c * THRN + tid] = (tid < m) ? sb[tid] : CUDART_INF_F;
    if (tid == 0) {
        g_m[c] = m; g_P[c] = P;
        g_wm[c] = (float)((double)K0 - a);
        g_tmax[c] = (m > 0) ? sb[m - 1] : -CUDART_INF_F;
    }
}

// ---------------- kernel 3: counting pass, ballot compaction ----------------
__global__ void __launch_bounds__(K3_THREADS, 2) k3(const float* __restrict__ pred,
                                                    const int*   __restrict__ tgt) {
    extern __shared__ unsigned char raw[];
    float* sthr = (float*)(raw + OFF_STHR);
    float* stmx = (float*)(raw + OFF_STMX);
    int*   sm_  = (int*)  (raw + OFF_SM);
    unsigned long long* acc64 = (unsigned long long*)(raw + OFF_ACC64);
    unsigned long long* qb    = (unsigned long long*)(raw + OFF_Q);

    const unsigned FULL = 0xffffffffu;
    int tid = threadIdx.x;
    for (int i = tid; i < NC * THRN; i += K3_THREADS) {
        int c = i / THRN, j = i - c * THRN;
        sthr[c * THRSTRIDE + j] = g_thr[i];
    }
    for (int i = tid; i < NC; i += K3_THREADS) {
        stmx[i] = g_tmax[i]; sm_[i] = g_m[i]; acc64[i] = 0ULL;
    }
    __syncthreads();

    int lane = tid & 31, wid = tid >> 5;
    unsigned long long* myq = qb + wid * QCAP;
    unsigned lt = (1u << lane) - 1u;

    float tm0 = -CUDART_INF_F, tm1 = -CUDART_INF_F, tm2 = -CUDART_INF_F, tm3 = -CUDART_INF_F;
    int c0 = 4 * lane;
    if (lane < 25) {
        tm0 = stmx[c0]; tm1 = stmx[c0 + 1]; tm2 = stmx[c0 + 2]; tm3 = stmx[c0 + 3];
    }

    int qn = 0;
    int warpGlobal = blockIdx.x * K3_WARPS + wid;
    const int stride = K3_BLOCKS * K3_WARPS;

    int row = warpGlobal;
    float4 v = make_float4(0.f, 0.f, 0.f, 0.f);
    if (row < NROWS && lane < 25) v = __ldg((const float4*)(pred + (size_t)row * NC) + lane);

    for (; row < NROWS; ) {
        int nrow = row + stride;
        float4 vn = make_float4(0.f, 0.f, 0.f, 0.f);
        if (nrow < NROWS && lane < 25) vn = __ldg((const float4*)(pred + (size_t)nrow * NC) + lane);

        float lse = __ldg(&g_lse[row]);
        int   t   = __ldg(&tgt[row]);

        float s0 = v.x - lse, s1 = v.y - lse, s2 = v.z - lse, s3 = v.w - lse;
        bool a0 = false, a1 = false, a2 = false, a3 = false;
        if (lane < 25) {
            a0 = (s0 < tm0) & (c0     != t);
            a1 = (s1 < tm1) & (c0 + 1 != t);
            a2 = (s2 < tm2) & (c0 + 2 != t);
            a3 = (s3 < tm3) & (c0 + 3 != t);
        }
        unsigned b0 = __ballot_sync(FULL, a0);
        unsigned b1 = __ballot_sync(FULL, a1);
        unsigned b2 = __ballot_sync(FULL, a2);
        unsigned b3 = __ballot_sync(FULL, a3);
        int n0 = __popc(b0), n1 = __popc(b1), n2 = __popc(b2), n3 = __popc(b3);
        int tot = n0 + n1 + n2 + n3;
        if (tot) {
            if (a0) myq[qn + __popc(b0 & lt)]                = ((unsigned long long)(c0    ) << 32) | (unsigned)__float_as_uint(s0);
            if (a1) myq[qn + n0 + __popc(b1 & lt)]           = ((unsigned long long)(c0 + 1) << 32) | (unsigned)__float_as_uint(s1);
            if (a2) myq[qn + n0 + n1 + __popc(b2 & lt)]      = ((unsigned long long)(c0 + 2) << 32) | (unsigned)__float_as_uint(s2);
            if (a3) myq[qn + n0 + n1 + n2 + __popc(b3 & lt)] = ((unsigned long long)(c0 + 3) << 32) | (unsigned)__float_as_uint(s3);
            qn += tot;
            __syncwarp();
            while (qn >= 32) {
                qn -= 32;
                unsigned long long ent = myq[qn + lane];
                int   c = (int)(ent >> 32);
                float s = __uint_as_float((unsigned)(ent & 0xffffffffu));
                int b = 0, tb = c * THRSTRIDE;
                #pragma unroll
                for (int st = 128; st; st >>= 1)
                    if (sthr[tb + b + st - 1] <= s) b += st;
                unsigned long long up = (1ULL << 32) | (unsigned)(sm_[c] - 1 - b);
                atomicAdd(&acc64[c], up);
            }
            __syncwarp();
        }
        v = vn; row = nrow;
    }
    __syncwarp();
    if (lane < qn) {
        unsigned long long ent = myq[lane];
        int   c = (int)(ent >> 32);
        float s = __uint_as_float((unsigned)(ent & 0xffffffffu));
        int b = 0, tb = c * THRSTRIDE;
        #pragma unroll
        for (int st = 128; st; st >>= 1)
            if (sthr[tb + b + st - 1] <= s) b += st;
        unsigned long long up = (1ULL << 32) | (unsigned)(sm_[c] - 1 - b);
        atomicAdd(&acc64[c], up);
    }
    __syncthreads();
    for (int i = tid; i < NC; i += K3_THREADS) {
        unsigned long long vv = acc64[i];
        if (vv) atomicAdd(&g_acc[i], vv);
    }
}

// ---------------- kernel 4: final combine ----------------
__global__ void __launch_bounds__(256) k4(const float* __restrict__ wt, float* __restrict__ out) {
    __shared__ double sd[256];
    int tid = threadIdx.x;

    double s = 0.0;
    for (int i = tid; i < K1_BLOCKS; i += 256) s += g_ce_part[i];
    sd[tid] = s; __syncthreads();
    for (int o = 128; o; o >>= 1) { if (tid < o) sd[tid] += sd[tid + o]; __syncthreads(); }
    double ce = sd[0] / (double)NROWS;
    __syncthreads();

    double pw = 0.0, wsum = 0.0;
    for (int c = tid; c < NC; c += 256) {
        int P = g_P[c], m = g_m[c];
        double pauc = 0.0;
        if (P > 0 && m > 0) {
            unsigned long long a = g_acc[c];
            double isum = (double)(unsigned)(a & 0xffffffffULL);
            double icnt = (double)(unsigned)(a >> 32);
            double Nn = (double)(NROWS - P);
            pauc = (isum + (double)g_wm[c] * icnt) / (Nn * (double)P);
        }
        double w = (double)wt[c];
        pw += pauc * w;
        wsum += w;
    }
    sd[tid] = pw; __syncthreads();
    for (int o = 128; o; o >>= 1) { if (tid < o) sd[tid] += sd[tid + o]; __syncthreads(); }
    double pwt = sd[0]; __syncthreads();
    sd[tid] = wsum; __syncthreads();
    for (int o = 128; o; o >>= 1) { if (tid < o) sd[tid] += sd[tid + o]; __syncthreads(); }
    double wst = sd[0];

    if (tid == 0) {
        double avg = pwt / (wst * 0.05);
        avg = fmin(fmax(avg, 0.0), 1.0);
        out[0] = (float)(0.5 * ce + 0.5 * (1.0 - avg * avg));
    }
}

// ---------------- launch ----------------
extern "C" void kernel_launch(void* const* d_in, const int* in_sizes, int n_in,
                              void* d_out, int out_size) {
    const float* pred = (const float*)d_in[0];
    const int*   tgt  = (const int*)d_in[1];
    const float* wt   = (const float*)d_in[2];
    float*       out  = (float*)d_out;

    cudaFuncSetAttribute(k3, cudaFuncAttributeMaxDynamicSharedMemorySize, K3_SMEM_BYTES);

    k_init<<<1, 128>>>();
    k1<<<K1_BLOCKS, K1_THREADS>>>(pred, tgt, wt);
    k2<<<NC, 1024>>>();
    k3<<<K3_BLOCKS, K3_THREADS, K3_SMEM_BYTES>>>(pred, tgt);
    k4<<<1, 256>>>(wt, out);
}

// round 9
// speedup vs baseline: 2.5297x; 1.8492x over previous
#include <cuda_runtime.h>
#include <math_constants.h>

#define NROWS 262144
#define NC 100
#define SUBW 32
#define SEGCAP 128
#define POSCAP (SUBW*SEGCAP)        // 4096 per class
#define THRN 192
#define THRSTRIDE 193
#define CAND 512

#define K1A_BLOCKS 2048
#define K1A_THREADS 256
#define K1A_RPW 16
#define K1B_BLOCKS 512
#define K1B_THREADS 512

#define K3_BLOCKS 296
#define K3_THREADS 1024
#define K3_WARPS (K3_THREADS/32)
#define QCAP 136

// k3 smem layout (bytes) — unchanged from round 8 (control)
#define OFF_STHR   0
#define OFF_STMX   (OFF_STHR + NC*THRSTRIDE*4)
#define OFF_SM     (OFF_STMX + NC*4)
#define OFF_ACC64  (OFF_SM + NC*4)
#define OFF_Q      (OFF_ACC64 + NC*8)
#define K3_SMEM_BYTES (OFF_Q + K3_WARPS*QCAP*8)

// ---------------- scratch ----------------
__device__ float  g_lse[NROWS];
__device__ float  g_ps_part[K1A_BLOCKS];
__device__ float  g_ce_part[K1B_BLOCKS];
__device__ int    g_cnt2[SUBW * 128];          // [sub*128 + c], 512B stride between subs
__device__ float  g_pos_buf[NC * POSCAP];      // [c*4096 + sub*128 + slot]
__device__ float  g_thr[NC * THRN];
__device__ float  g_tmax[NC];
__device__ float  g_wm[NC];
__device__ int    g_m[NC];
__device__ int    g_P[NC];
__device__ unsigned long long g_acc[NC];

__device__ __forceinline__ float ex2f(float x) {
    float y; asm("ex2.approx.f32 %0, %1;" : "=f"(y) : "f"(x)); return y;
}
__device__ __forceinline__ float lg2f(float x) {
    float y; asm("lg2.approx.f32 %0, %1;" : "=f"(y) : "f"(x)); return y;
}
__device__ __forceinline__ unsigned monokey(float s) {
    unsigned u = __float_as_uint(s);
    return u ^ ((((int)u) >> 31) | 0x80000000u);
}

// ---------------- kernel 0: init ----------------
__global__ void k_init() {
    int i = blockIdx.x * blockDim.x + threadIdx.x;
    if (i < SUBW * 128) g_cnt2[i] = 0;
    if (i < NC) g_acc[i] = 0ULL;
}

// ---------------- kernel 1a: pure streaming lse + sum(w*x) ----------------
__global__ void __launch_bounds__(K1A_THREADS) k1a(const float* __restrict__ pred,
                                                   const float* __restrict__ wt) {
    const float L2E = 1.4426950408889634f;
    const float LN2 = 0.6931471805599453f;
    const unsigned FULL = 0xffffffffu;
    int lane = threadIdx.x & 31;
    int wid  = threadIdx.x >> 5;
    int warpGlobal = blockIdx.x * (K1A_THREADS / 32) + wid;
    int row0 = warpGlobal * K1A_RPW;

    float4 wv = make_float4(0.f, 0.f, 0.f, 0.f);
    if (lane < 25) wv = __ldg((const float4*)wt + lane);

    float ps = 0.f;

    #pragma unroll 1
    for (int it = 0; it < K1A_RPW / 4; ++it) {
        float4 v[4];
        float  e[4];
        #pragma unroll
        for (int k = 0; k < 4; ++k) {
            int row = row0 + it * 4 + k;
            v[k] = make_float4(0.f, 0.f, 0.f, 0.f);
            if (lane < 25) v[k] = __ldg((const float4*)(pred + (size_t)row * NC) + lane);
        }
        #pragma unroll
        for (int k = 0; k < 4; ++k) {
            e[k] = 0.f;
            if (lane < 25) {
                e[k] = ex2f(v[k].x * L2E) + ex2f(v[k].y * L2E)
                     + ex2f(v[k].z * L2E) + ex2f(v[k].w * L2E);
                ps  += wv.x * v[k].x + wv.y * v[k].y + wv.z * v[k].z + wv.w * v[k].w;
            }
        }
        #pragma unroll
        for (int o = 16; o; o >>= 1) {
            #pragma unroll
            for (int k = 0; k < 4; ++k) e[k] += __shfl_xor_sync(FULL, e[k], o);
        }
        if (lane < 4) {
            int row = row0 + it * 4 + lane;
            g_lse[row] = lg2f(e[lane]) * LN2;
        }
    }

    #pragma unroll
    for (int o = 16; o; o >>= 1) ps += __shfl_xor_sync(FULL, ps, o);
    __shared__ float sps[K1A_THREADS / 32];
    if (lane == 0) sps[wid] = ps;
    __syncthreads();
    if (threadIdx.x == 0) {
        float s = 0.f;
        #pragma unroll
        for (int i = 0; i < K1A_THREADS / 32; ++i) s += sps[i];
        g_ps_part[blockIdx.x] = s;
    }
}

// ---------------- kernel 1b: per-row CE + positive scatter ----------------
__global__ void __launch_bounds__(K1B_THREADS) k1b(const float* __restrict__ pred,
                                                   const int*   __restrict__ tgt,
                                                   const float* __restrict__ wt) {
    __shared__ float sW;
    __shared__ float sred[K1B_THREADS / 32];
    int tid = threadIdx.x, lane = tid & 31, wid = tid >> 5;
    const unsigned FULL = 0xffffffffu;

    if (wid == 0) {
        float4 wv = make_float4(0.f, 0.f, 0.f, 0.f);
        if (lane < 25) wv = __ldg((const float4*)wt + lane);
        float W = wv.x + wv.y + wv.z + wv.w;
        #pragma unroll
        for (int o = 16; o; o >>= 1) W += __shfl_xor_sync(FULL, W, o);
        if (lane == 0) sW = W;
    }
    __syncthreads();
    float W = sW;

    int row = blockIdx.x * K1B_THREADS + tid;
    int   t   = __ldg(&tgt[row]);
    float lse = __ldg(&g_lse[row]);
    float xt  = __ldg(pred + (size_t)row * NC + t);
    float wtt = __ldg(&wt[t]);

    int sub = blockIdx.x & (SUBW - 1);
    int slot = atomicAdd(&g_cnt2[sub * 128 + t], 1);
    if (slot < SEGCAP) g_pos_buf[t * POSCAP + sub * SEGCAP + slot] = xt - lse;

    float ce = 0.9f * wtt * (lse - xt) + 0.001f * W * lse;
    #pragma unroll
    for (int o = 16; o; o >>= 1) ce += __shfl_xor_sync(FULL, ce, o);
    if (lane == 0) sred[wid] = ce;
    __syncthreads();
    if (tid == 0) {
        float s = 0.f;
        #pragma unroll
        for (int i = 0; i < K1B_THREADS / 32; ++i) s += sred[i];
        g_ce_part[blockIdx.x] = s;
    }
}

// ---------------- kernel 2: histogram selection of bottom-m + small sort ----------------
__global__ void __launch_bounds__(256) k2() {
    __shared__ float    vals[POSCAP];       // 16KB
    __shared__ unsigned hist[2048];         // 8KB
    __shared__ int      scnt[SUBW];
    __shared__ int      soff[SUBW + 1];
    __shared__ int      spart[256];
    __shared__ int      sB, sBase, sCtr;
    __shared__ float    cand[CAND];

    int c = blockIdx.x, tid = threadIdx.x;

    // gather segment counts + offsets
    if (tid < SUBW) {
        int n = g_cnt2[tid * 128 + c];
        scnt[tid] = (n > SEGCAP) ? SEGCAP : n;
    }
    __syncthreads();
    if (tid == 0) {
        int run = 0;
        #pragma unroll
        for (int s = 0; s < SUBW; ++s) { soff[s] = run; run += scnt[s]; }
        soff[SUBW] = run;
    }
    __syncthreads();
    int P = soff[SUBW];

    // compact values
    for (int idx = tid; idx < SUBW * SEGCAP; idx += 256) {
        int s = idx >> 7, sl = idx & 127;
        if (sl < scnt[s]) vals[soff[s] + sl] = g_pos_buf[c * POSCAP + s * SEGCAP + sl];
    }
    __syncthreads();

    double a  = 0.95 * (double)P;
    int    K0 = (int)floor(a) + 1;
    int    m  = P - K0 + 1;
    if (m < 0) m = 0;
    if (m > THRN) m = THRN;

    if (m == 0 || P == 0) {
        if (tid < THRN) g_thr[c * THRN + tid] = CUDART_INF_F;
        if (tid == 0) {
            g_m[c] = 0; g_P[c] = P; g_wm[c] = 0.f; g_tmax[c] = -CUDART_INF_F;
        }
        return;
    }

    // ---- level 1: histogram of key>>21 ----
    for (int i = tid; i < 2048; i += 256) hist[i] = 0u;
    __syncthreads();
    for (int i = tid; i < P; i += 256) atomicAdd(&hist[monokey(vals[i]) >> 21], 1u);
    __syncthreads();
    {
        int part = 0;
        #pragma unroll
        for (int k = 0; k < 8; ++k) part += (int)hist[tid * 8 + k];
        spart[tid] = part;
        __syncthreads();
        for (int off = 1; off < 256; off <<= 1) {
            int v = (tid >= off) ? spart[tid - off] : 0;
            __syncthreads();
            spart[tid] += v;
            __syncthreads();
        }
        int excl = spart[tid] - part;
        if (excl < m && m <= spart[tid]) {
            int run = excl;
            #pragma unroll
            for (int k = 0; k < 8; ++k) {
                int h = (int)hist[tid * 8 + k];
                if (run + h >= m) { sB = tid * 8 + k; sBase = run; break; }
                run += h;
            }
        }
    }
    __syncthreads();
    int B1 = sB, base1 = sBase;

    // ---- level 2: histogram of (key>>10)&0x7ff within bucket B1 ----
    for (int i = tid; i < 2048; i += 256) hist[i] = 0u;
    __syncthreads();
    for (int i = tid; i < P; i += 256) {
        unsigned k = monokey(vals[i]);
        if ((int)(k >> 21) == B1) atomicAdd(&hist[(k >> 10) & 0x7ffu], 1u);
    }
    __syncthreads();
    int r2 = m - base1;
    {
        int part = 0;
        #pragma unroll
        for (int k = 0; k < 8; ++k) part += (int)hist[tid * 8 + k];
        spart[tid] = part;
        __syncthreads();
        for (int off = 1; off < 256; off <<= 1) {
            int v = (tid >= off) ? spart[tid - off] : 0;
            __syncthreads();
            spart[tid] += v;
            __syncthreads();
        }
        int excl = spart[tid] - part;
        if (excl < r2 && r2 <= spart[tid]) {
            int run = excl;
            #pragma unroll
            for (int k = 0; k < 8; ++k) {
                int h = (int)hist[tid * 8 + k];
                if (run + h >= r2) { sB = tid * 8 + k; break; }
                run += h;
            }
        }
        if (tid == 0) sCtr = 0;
    }
    __syncthreads();
    unsigned bound = ((unsigned)B1 << 11) | (unsigned)sB;   // on key>>10

    // ---- gather candidates (all keys with key>>10 <= bound) ----
    for (int i = tid; i < P; i += 256) {
        float v = vals[i];
        if ((monokey(v) >> 10) <= bound) {
            int p = atomicAdd(&sCtr, 1);
            if (p < CAND) cand[p] = v;
        }
    }
    __syncthreads();
    int nc = sCtr; if (nc > CAND) nc = CAND;
    for (int i = tid; i < CAND; i += 256) if (i >= nc) cand[i] = CUDART_INF_F;
    __syncthreads();

    // ---- bitonic sort 512 candidates ----
    for (int k = 2; k <= CAND; k <<= 1) {
        for (int j = k >> 1; j > 0; j >>= 1) {
            for (int i = tid; i < CAND; i += 256) {
                int ixj = i ^ j;
                if (ixj > i) {
                    float x = cand[i], y = cand[ixj];
                    bool up = ((i & k) == 0);
                    if ((x > y) == up) { cand[i] = y; cand[ixj] = x; }
                }
            }
            __syncthreads();
        }
    }

    if (tid < THRN) g_thr[c * THRN + tid] = (tid < m) ? cand[tid] : CUDART_INF_F;
    if (tid == 0) {
        g_m[c] = m; g_P[c] = P;
        g_wm[c] = (float)((double)K0 - a);
        g_tmax[c] = cand[m - 1];
    }
}

// ---------------- kernel 3: counting pass (unchanged control) ----------------
__global__ void __launch_bounds__(K3_THREADS, 2) k3(const float* __restrict__ pred,
                                                    const int*   __restrict__ tgt) {
    extern __shared__ unsigned char raw[];
    float* sthr = (float*)(raw + OFF_STHR);
    float* stmx = (float*)(raw + OFF_STMX);
    int*   sm_  = (int*)  (raw + OFF_SM);
    unsigned long long* acc64 = (unsigned long long*)(raw + OFF_ACC64);
    unsigned long long* qb    = (unsigned long long*)(raw + OFF_Q);

    const unsigned FULL = 0xffffffffu;
    int tid = threadIdx.x;
    for (int i = tid; i < NC * THRN; i += K3_THREADS) {
        int c = i / THRN, j = i - c * THRN;
        sthr[c * THRSTRIDE + j] = g_thr[i];
    }
    for (int i = tid; i < NC; i += K3_THREADS) {
        stmx[i] = g_tmax[i]; sm_[i] = g_m[i]; acc64[i] = 0ULL;
    }
    __syncthreads();

    int lane = tid & 31, wid = tid >> 5;
    unsigned long long* myq = qb + wid * QCAP;
    unsigned lt = (1u << lane) - 1u;

    float tm0 = -CUDART_INF_F, tm1 = -CUDART_INF_F, tm2 = -CUDART_INF_F, tm3 = -CUDART_INF_F;
    int c0 = 4 * lane;
    if (lane < 25) {
        tm0 = stmx[c0]; tm1 = stmx[c0 + 1]; tm2 = stmx[c0 + 2]; tm3 = stmx[c0 + 3];
    }

    int qn = 0;
    int warpGlobal = blockIdx.x * K3_WARPS + wid;
    const int stride = K3_BLOCKS * K3_WARPS;

    int row = warpGlobal;
    float4 v = make_float4(0.f, 0.f, 0.f, 0.f);
    if (row < NROWS && lane < 25) v = __ldg((const float4*)(pred + (size_t)row * NC) + lane);

    for (; row < NROWS; ) {
        int nrow = row + stride;
        float4 vn = make_float4(0.f, 0.f, 0.f, 0.f);
        if (nrow < NROWS && lane < 25) vn = __ldg((const float4*)(pred + (size_t)nrow * NC) + lane);

        float lse = __ldg(&g_lse[row]);
        int   t   = __ldg(&tgt[row]);

        float s0 = v.x - lse, s1 = v.y - lse, s2 = v.z - lse, s3 = v.w - lse;
        bool a0 = false, a1 = false, a2 = false, a3 = false;
        if (lane < 25) {
            a0 = (s0 < tm0) & (c0     != t);
            a1 = (s1 < tm1) & (c0 + 1 != t);
            a2 = (s2 < tm2) & (c0 + 2 != t);
            a3 = (s3 < tm3) & (c0 + 3 != t);
        }
        unsigned b0 = __ballot_sync(FULL, a0);
        unsigned b1 = __ballot_sync(FULL, a1);
        unsigned b2 = __ballot_sync(FULL, a2);
        unsigned b3 = __ballot_sync(FULL, a3);
        int n0 = __popc(b0), n1 = __popc(b1), n2 = __popc(b2), n3 = __popc(b3);
        int tot = n0 + n1 + n2 + n3;
        if (tot) {
            if (a0) myq[qn + __popc(b0 & lt)]                = ((unsigned long long)(c0    ) << 32) | (unsigned)__float_as_uint(s0);
            if (a1) myq[qn + n0 + __popc(b1 & lt)]           = ((unsigned long long)(c0 + 1) << 32) | (unsigned)__float_as_uint(s1);
            if (a2) myq[qn + n0 + n1 + __popc(b2 & lt)]      = ((unsigned long long)(c0 + 2) << 32) | (unsigned)__float_as_uint(s2);
            if (a3) myq[qn + n0 + n1 + n2 + __popc(b3 & lt)] = ((unsigned long long)(c0 + 3) << 32) | (unsigned)__float_as_uint(s3);
            qn += tot;
            __syncwarp();
            while (qn >= 32) {
                qn -= 32;
                unsigned long long ent = myq[qn + lane];
                int   c = (int)(ent >> 32);
                float s = __uint_as_float((unsigned)(ent & 0xffffffffu));
                int b = 0, tb = c * THRSTRIDE;
                #pragma unroll
                for (int st = 128; st; st >>= 1)
                    if (sthr[tb + b + st - 1] <= s) b += st;
                unsigned long long up = (1ULL << 32) | (unsigned)(sm_[c] - 1 - b);
                atomicAdd(&acc64[c], up);
            }
            __syncwarp();
        }
        v = vn; row = nrow;
    }
    __syncwarp();
    if (lane < qn) {
        unsigned long long ent = myq[lane];
        int   c = (int)(ent >> 32);
        float s = __uint_as_float((unsigned)(ent & 0xffffffffu));
        int b = 0, tb = c * THRSTRIDE;
        #pragma unroll
        for (int st = 128; st; st >>= 1)
            if (sthr[tb + b + st - 1] <= s) b += st;
        unsigned long long up = (1ULL << 32) | (unsigned)(sm_[c] - 1 - b);
        atomicAdd(&acc64[c], up);
    }
    __syncthreads();
    for (int i = tid; i < NC; i += K3_THREADS) {
        unsigned long long vv = acc64[i];
        if (vv) atomicAdd(&g_acc[i], vv);
    }
}

// ---------------- kernel 4: final combine ----------------
__global__ void __launch_bounds__(256) k4(const float* __restrict__ wt, float* __restrict__ out) {
    __shared__ double sd[256];
    int tid = threadIdx.x;

    double s = 0.0;
    for (int i = tid; i < K1B_BLOCKS; i += 256) s += (double)g_ce_part[i];
    for (int i = tid; i < K1A_BLOCKS; i += 256) s -= 0.001 * (double)g_ps_part[i];
    sd[tid] = s; __syncthreads();
    for (int o = 128; o; o >>= 1) { if (tid < o) sd[tid] += sd[tid + o]; __syncthreads(); }
    double ce = sd[0] / (double)NROWS;
    __syncthreads();

    double pw = 0.0, wsum = 0.0;
    for (int c = tid; c < NC; c += 256) {
        int P = g_P[c], m = g_m[c];
        double pauc = 0.0;
        if (P > 0 && m > 0) {
            unsigned long long a = g_acc[c];
            double isum = (double)(unsigned)(a & 0xffffffffULL);
            double icnt = (double)(unsigned)(a >> 32);
            double Nn = (double)(NROWS - P);
            pauc = (isum + (double)g_wm[c] * icnt) / (Nn * (double)P);
        }
        double w = (double)wt[c];
        pw += pauc * w;
        wsum += w;
    }
    sd[tid] = pw; __syncthreads();
    for (int o = 128; o; o >>= 1) { if (tid < o) sd[tid] += sd[tid + o]; __syncthreads(); }
    double pwt = sd[0]; __syncthreads();
    sd[tid] = wsum; __syncthreads();
    for (int o = 128; o; o >>= 1) { if (tid < o) sd[tid] += sd[tid + o]; __syncthreads(); }
    double wst = sd[0];

    if (tid == 0) {
        double avg = pwt / (wst * 0.05);
        avg = fmin(fmax(avg, 0.0), 1.0);
        out[0] = (float)(0.5 * ce + 0.5 * (1.0 - avg * avg));
    }
}

// ---------------- launch ----------------
extern "C" void kernel_launch(void* const* d_in, const int* in_sizes, int n_in,
                              void* d_out, int out_size) {
    const float* pred = (const float*)d_in[0];
    const int*   tgt  = (const int*)d_in[1];
    const float* wt   = (const float*)d_in[2];
    float*       out  = (float*)d_out;

    cudaFuncSetAttribute(k3, cudaFuncAttributeMaxDynamicSharedMemorySize, K3_SMEM_BYTES);

    k_init<<<16, 256>>>();
    k1a<<<K1A_BLOCKS, K1A_THREADS>>>(pred, wt);
    k1b<<<K1B_BLOCKS, K1B_THREADS>>>(pred, tgt, wt);
    k2<<<NC, 256>>>();
    k3<<<K3_BLOCKS, K3_THREADS, K3_SMEM_BYTES>>>(pred, tgt);
    k4<<<1, 256>>>(wt, out);
}

// round 11
// speedup vs baseline: 2.8118x; 1.1115x over previous
#include <cuda_runtime.h>
#include <math_constants.h>

#define NROWS 262144
#define NC 100
#define SUBW 32
#define SEGCAP 128
#define POSCAP (SUBW*SEGCAP)
#define THRN 192
#define THRSTRIDE 193
#define CAND 512

#define K1A_BLOCKS 2048
#define K1A_THREADS 256
#define K1A_RPW 16
#define K1B_BLOCKS 512
#define K1B_THREADS 512

#define K3_BLOCKS 296
#define K3_THREADS 1024
#define K3_WARPS (K3_THREADS/32)
#define QCAP 136

#define OFF_STHR   0
#define OFF_STMX   (OFF_STHR + NC*THRSTRIDE*4)
#define OFF_SM     (OFF_STMX + NC*4)
#define OFF_ACC64  (OFF_SM + NC*4)
#define OFF_Q      (OFF_ACC64 + NC*8)
#define K3_SMEM_BYTES (OFF_Q + K3_WARPS*QCAP*8)

// ---------------- scratch ----------------
__device__ float  g_lse[NROWS];
__device__ float  g_ps[NROWS];              // xt - lse per row
__device__ float  g_ps_part[K1A_BLOCKS];
__device__ float  g_ce_part[K1B_BLOCKS];
__device__ int    g_cnt2[SUBW * 128];
__device__ float  g_pos_buf[NC * POSCAP];
__device__ float  g_thr[NC * THRN];
__device__ float  g_tmax[NC];
__device__ float  g_wm[NC];
__device__ int    g_m[NC];
__device__ int    g_P[NC];
__device__ unsigned long long g_acc[NC];
__device__ unsigned long long g_corr[NC];

__device__ __forceinline__ float ex2f(float x) {
    float y; asm("ex2.approx.f32 %0, %1;" : "=f"(y) : "f"(x)); return y;
}
__device__ __forceinline__ float lg2f(float x) {
    float y; asm("lg2.approx.f32 %0, %1;" : "=f"(y) : "f"(x)); return y;
}
__device__ __forceinline__ unsigned monokey(float s) {
    unsigned u = __float_as_uint(s);
    return u ^ ((((int)u) >> 31) | 0x80000000u);
}

// ---------------- kernel 0: init ----------------
__global__ void k_init() {
    int i = blockIdx.x * blockDim.x + threadIdx.x;
    if (i < SUBW * 128) g_cnt2[i] = 0;
    if (i < NC) { g_acc[i] = 0ULL; g_corr[i] = 0ULL; }
}

// ---------------- kernel 1a: streaming lse + sum(w*x) + target extract ----------------
__global__ void __launch_bounds__(K1A_THREADS) k1a(const float* __restrict__ pred,
                                                   const int*   __restrict__ tgt,
                                                   const float* __restrict__ wt) {
    const float L2E = 1.4426950408889634f;
    const float LN2 = 0.6931471805599453f;
    const unsigned FULL = 0xffffffffu;
    int lane = threadIdx.x & 31;
    int wid  = threadIdx.x >> 5;
    int warpGlobal = blockIdx.x * (K1A_THREADS / 32) + wid;
    int row0 = warpGlobal * K1A_RPW;

    float4 wv = make_float4(0.f, 0.f, 0.f, 0.f);
    if (lane < 25) wv = __ldg((const float4*)wt + lane);

    int tA = (lane < K1A_RPW) ? __ldg(&tgt[row0 + lane]) : 0;

    float ps = 0.f;

    #pragma unroll 1
    for (int it = 0; it < K1A_RPW / 4; ++it) {
        float4 v[4];
        float  e[4];
        float  xt[4];
        int    t4[4];
        #pragma unroll
        for (int k = 0; k < 4; ++k) {
            int row = row0 + it * 4 + k;
            v[k] = make_float4(0.f, 0.f, 0.f, 0.f);
            if (lane < 25) v[k] = __ldg((const float4*)(pred + (size_t)row * NC) + lane);
            t4[k] = __shfl_sync(FULL, tA, it * 4 + k);
        }
        #pragma unroll
        for (int k = 0; k < 4; ++k) {
            e[k] = 0.f;
            if (lane < 25) {
                e[k] = ex2f(v[k].x * L2E) + ex2f(v[k].y * L2E)
                     + ex2f(v[k].z * L2E) + ex2f(v[k].w * L2E);
                ps  += wv.x * v[k].x + wv.y * v[k].y + wv.z * v[k].z + wv.w * v[k].w;
            }
            int sl = t4[k] & 3;
            float xo = (sl == 0) ? v[k].x : (sl == 1) ? v[k].y : (sl == 2) ? v[k].z : v[k].w;
            xt[k] = __shfl_sync(FULL, xo, t4[k] >> 2);
        }
        #pragma unroll
        for (int o = 16; o; o >>= 1) {
            #pragma unroll
            for (int k = 0; k < 4; ++k) e[k] += __shfl_xor_sync(FULL, e[k], o);
        }
        #pragma unroll
        for (int k = 0; k < 4; ++k) {
            float ls = lg2f(e[k]) * LN2;
            if (lane == k) {
                int row = row0 + it * 4 + k;
                g_lse[row] = ls;
                g_ps[row]  = xt[k] - ls;
            }
        }
    }

    #pragma unroll
    for (int o = 16; o; o >>= 1) ps += __shfl_xor_sync(FULL, ps, o);
    __shared__ float sps[K1A_THREADS / 32];
    if (lane == 0) sps[wid] = ps;
    __syncthreads();
    if (threadIdx.x == 0) {
        float s = 0.f;
        #pragma unroll
        for (int i = 0; i < K1A_THREADS / 32; ++i) s += sps[i];
        g_ps_part[blockIdx.x] = s;
    }
}

// ---------------- kernel 1b: CE + positive scatter (no pred reads) ----------------
__global__ void __launch_bounds__(K1B_THREADS) k1b(const int*   __restrict__ tgt,
                                                   const float* __restrict__ wt) {
    __shared__ float sW;
    __shared__ float sred[K1B_THREADS / 32];
    int tid = threadIdx.x, lane = tid & 31, wid = tid >> 5;
    const unsigned FULL = 0xffffffffu;

    if (wid == 0) {
        float4 wv = make_float4(0.f, 0.f, 0.f, 0.f);
        if (lane < 25) wv = __ldg((const float4*)wt + lane);
        float W = wv.x + wv.y + wv.z + wv.w;
        #pragma unroll
        for (int o = 16; o; o >>= 1) W += __shfl_xor_sync(FULL, W, o);
        if (lane == 0) sW = W;
    }
    __syncthreads();
    float W = sW;

    int row = blockIdx.x * K1B_THREADS + tid;
    int   t   = __ldg(&tgt[row]);
    float s   = __ldg(&g_ps[row]);
    float lse = __ldg(&g_lse[row]);
    float wtt = __ldg(&wt[t]);

    int sub = blockIdx.x & (SUBW - 1);
    int slot = atomicAdd(&g_cnt2[sub * 128 + t], 1);
    if (slot < SEGCAP) g_pos_buf[t * POSCAP + sub * SEGCAP + slot] = s;

    float ce = -0.9f * wtt * s + 0.001f * W * lse;
    #pragma unroll
    for (int o = 16; o; o >>= 1) ce += __shfl_xor_sync(FULL, ce, o);
    if (lane == 0) sred[wid] = ce;
    __syncthreads();
    if (tid == 0) {
        float sr = 0.f;
        #pragma unroll
        for (int i = 0; i < K1B_THREADS / 32; ++i) sr += sred[i];
        g_ce_part[blockIdx.x] = sr;
    }
}

// ---------------- kernel 2: selection with shfl scans (1024 thr) ----------------
__global__ void __launch_bounds__(1024) k2() {
    __shared__ float    vals[POSCAP];
    __shared__ unsigned hist[2048];
    __shared__ int      scnt[SUBW];
    __shared__ int      soff[SUBW + 1];
    __shared__ int      warpsum[32];
    __shared__ int      sB, sBase, sCtr;
    __shared__ float    cand[CAND];

    int c = blockIdx.x, tid = threadIdx.x, lane = tid & 31, wid = tid >> 5;
    const unsigned FULL = 0xffffffffu;

    if (tid < 32) {
        int n = g_cnt2[tid * 128 + c];
        if (n > SEGCAP) n = SEGCAP;
        scnt[tid] = n;
        int x = n;
        #pragma unroll
        for (int o = 1; o < 32; o <<= 1) {
            int y = __shfl_up_sync(FULL, x, o);
            if (lane >= o) x += y;
        }
        soff[tid + 1] = x;
        if (tid == 0) soff[0] = 0;
    }
    __syncthreads();
    int P = soff[32];

    for (int idx = tid; idx < SUBW * SEGCAP; idx += 1024) {
        int s = idx >> 7, sl = idx & 127;
        if (sl < scnt[s]) vals[soff[s] + sl] = g_pos_buf[c * POSCAP + s * SEGCAP + sl];
    }

    double a  = 0.95 * (double)P;
    int    K0 = (int)floor(a) + 1;
    int    m  = P - K0 + 1;
    if (m < 0) m = 0;
    if (m > THRN) m = THRN;

    if (m == 0 || P == 0) {
        if (tid < THRN) g_thr[c * THRN + tid] = CUDART_INF_F;
        if (tid == 0) { g_m[c] = 0; g_P[c] = P; g_wm[c] = 0.f; g_tmax[c] = -CUDART_INF_F; }
        return;
    }

    // ===== level 1: histogram on key>>21 =====
    for (int i = tid; i < 2048; i += 1024) hist[i] = 0u;
    __syncthreads();
    for (int i = tid; i < P; i += 1024) atomicAdd(&hist[monokey(vals[i]) >> 21], 1u);
    __syncthreads();
    {
        int b0 = (int)hist[2 * tid], b1 = (int)hist[2 * tid + 1];
        int loc = b0 + b1;
        int x = loc;
        #pragma unroll
        for (int o = 1; o < 32; o <<= 1) {
            int y = __shfl_up_sync(FULL, x, o);
            if (lane >= o) x += y;
        }
        if (lane == 31) warpsum[wid] = x;
        __syncthreads();
        if (wid == 0) {
            int w = warpsum[lane];
            #pragma unroll
            for (int o = 1; o < 32; o <<= 1) {
                int y = __shfl_up_sync(FULL, w, o);
                if (lane >= o) w += y;
            }
            warpsum[lane] = w;
        }
        __syncthreads();
        int base = (wid ? warpsum[wid - 1] : 0) + x - loc;
        if (base < m && m <= base + b0) { sB = 2 * tid; sBase = base; }
        else if (base + b0 < m && m <= base + loc) { sB = 2 * tid + 1; sBase = base + b0; }
    }
    __syncthreads();
    int B1 = sB, base1 = sBase;

    // ===== level 2: histogram on (key>>10)&0x7ff within bucket B1 =====
    for (int i = tid; i < 2048; i += 1024) hist[i] = 0u;
    __syncthreads();
    for (int i = tid; i < P; i += 1024) {
        unsigned k = monokey(vals[i]);
        if ((int)(k >> 21) == B1) atomicAdd(&hist[(k >> 10) & 0x7ffu], 1u);
    }
    __syncthreads();
    int r2 = m - base1;
    {
        int b0 = (int)hist[2 * tid], b1 = (int)hist[2 * tid + 1];
        int loc = b0 + b1;
        int x = loc;
        #pragma unroll
        for (int o = 1; o < 32; o <<= 1) {
            int y = __shfl_up_sync(FULL, x, o);
            if (lane >= o) x += y;
        }
        if (lane == 31) warpsum[wid] = x;
        __syncthreads();
        if (wid == 0) {
            int w = warpsum[lane];
            #pragma unroll
            for (int o = 1; o < 32; o <<= 1) {
                int y = __shfl_up_sync(FULL, w, o);
                if (lane >= o) w += y;
            }
            warpsum[lane] = w;
        }
        __syncthreads();
        int base = (wid ? warpsum[wid - 1] : 0) + x - loc;
        if (base < r2 && r2 <= base + b0) sB = 2 * tid;
        else if (base + b0 < r2 && r2 <= base + loc) sB = 2 * tid + 1;
        if (tid == 0) sCtr = 0;
    }
    __syncthreads();
    unsigned bound = ((unsigned)B1 << 11) | (unsigned)sB;

    for (int i = tid; i < P; i += 1024) {
        float v = vals[i];
        if ((monokey(v) >> 10) <= bound) {
            int p = atomicAdd(&sCtr, 1);
            if (p < CAND) cand[p] = v;
        }
    }
    __syncthreads();
    int ncand = sCtr; if (ncand > CAND) ncand = CAND;
    for (int i = tid; i < CAND; i += 1024) if (i >= ncand) cand[i] = CUDART_INF_F;
    __syncthreads();

    for (int k = 2; k <= CAND; k <<= 1) {
        for (int j = k >> 1; j > 0; j >>= 1) {
            if (tid < CAND) {
                int i = tid, ixj = i ^ j;
                if (ixj > i) {
                    float x = cand[i], y = cand[ixj];
                    bool up = ((i & k) == 0);
                    if ((x > y) == up) { cand[i] = y; cand[ixj] = x; }
                }
            }
            __syncthreads();
        }
    }

    if (tid < THRN) g_thr[c * THRN + tid] = (tid < m) ? cand[tid] : CUDART_INF_F;
    if (tid == 0) {
        g_m[c] = m; g_P[c] = P;
        g_wm[c] = (float)((double)K0 - a);
        g_tmax[c] = cand[m - 1];
    }
}

// ---------------- kernel 3fix: subtract target-pair contributions ----------------
__global__ void __launch_bounds__(512) k3f(const int* __restrict__ tgt) {
    int row = blockIdx.x * 512 + threadIdx.x;
    int   t = __ldg(&tgt[row]);
    float s = __ldg(&g_ps[row]);
    if (s < __ldg(&g_tmax[t])) {
        int b = 0, tb = t * THRN;
        #pragma unroll
        for (int st = 128; st; st >>= 1)
            if (__ldg(&g_thr[tb + b + st - 1]) <= s) b += st;
        unsigned long long up = (1ULL << 32) | (unsigned)(__ldg(&g_m[t]) - 1 - b);
        atomicAdd(&g_corr[t], up);
    }
}

// ---------------- kernel 3: counting pass (no target check) ----------------
__global__ void __launch_bounds__(K3_THREADS, 2) k3(const float* __restrict__ pred) {
    extern __shared__ unsigned char raw[];
    float* sthr = (float*)(raw + OFF_STHR);
    float* stmx = (float*)(raw + OFF_STMX);
    int*   sm_  = (int*)  (raw + OFF_SM);
    unsigned long long* acc64 = (unsigned long long*)(raw + OFF_ACC64);
    unsigned long long* qb    = (unsigned long long*)(raw + OFF_Q);

    const unsigned FULL = 0xffffffffu;
    int tid = threadIdx.x;
    for (int i = tid; i < NC * THRN; i += K3_THREADS) {
        int c = i / THRN, j = i - c * THRN;
        sthr[c * THRSTRIDE + j] = g_thr[i];
    }
    for (int i = tid; i < NC; i += K3_THREADS) {
        stmx[i] = g_tmax[i]; sm_[i] = g_m[i]; acc64[i] = 0ULL;
    }
    __syncthreads();

    int lane = tid & 31, wid = tid >> 5;
    unsigned long long* myq = qb + wid * QCAP;
    unsigned lt = (1u << lane) - 1u;

    float tm0 = -CUDART_INF_F, tm1 = -CUDART_INF_F, tm2 = -CUDART_INF_F, tm3 = -CUDART_INF_F;
    int c0 = 4 * lane;
    if (lane < 25) {
        tm0 = stmx[c0]; tm1 = stmx[c0 + 1]; tm2 = stmx[c0 + 2]; tm3 = stmx[c0 + 3];
    }

    int qn = 0;
    int warpGlobal = blockIdx.x * K3_WARPS + wid;
    const int stride = K3_BLOCKS * K3_WARPS;

    int row = warpGlobal;
    float4 v = make_float4(0.f, 0.f, 0.f, 0.f);
    if (row < NROWS && lane < 25) v = __ldg((const float4*)(pred + (size_t)row * NC) + lane);

    for (; row < NROWS; ) {
        int nrow = row + stride;
        float4 vn = make_float4(0.f, 0.f, 0.f, 0.f);
        if (nrow < NROWS && lane < 25) vn = __ldg((const float4*)(pred + (size_t)nrow * NC) + lane);

        float lse = __ldg(&g_lse[row]);

        float s0 = v.x - lse, s1 = v.y - lse, s2 = v.z - lse, s3 = v.w - lse;
        bool a0 = s0 < tm0, a1 = s1 < tm1, a2 = s2 < tm2, a3 = s3 < tm3;

        unsigned b0 = __ballot_sync(FULL, a0);
        unsigned b1 = __ballot_sync(FULL, a1);
        unsigned b2 = __ballot_sync(FULL, a2);
        unsigned b3 = __ballot_sync(FULL, a3);
        int n0 = __popc(b0), n1 = __popc(b1), n2 = __popc(b2), n3 = __popc(b3);
        int tot = n0 + n1 + n2 + n3;
        if (tot) {
            if (a0) myq[qn + __popc(b0 & lt)]                = ((unsigned long long)(c0    ) << 32) | (unsigned)__float_as_uint(s0);
            if (a1) myq[qn + n0 + __popc(b1 & lt)]           = ((unsigned long long)(c0 + 1) << 32) | (unsigned)__float_as_uint(s1);
            if (a2) myq[qn + n0 + n1 + __popc(b2 & lt)]      = ((unsigned long long)(c0 + 2) << 32) | (unsigned)__float_as_uint(s2);
            if (a3) myq[qn + n0 + n1 + n2 + __popc(b3 & lt)] = ((unsigned long long)(c0 + 3) << 32) | (unsigned)__float_as_uint(s3);
            qn += tot;
            __syncwarp();
            while (qn >= 32) {
                qn -= 32;
                unsigned long long ent = myq[qn + lane];
                int   c = (int)(ent >> 32);
                float s = __uint_as_float((unsigned)(ent & 0xffffffffu));
                int b = 0, tb = c * THRSTRIDE;
                #pragma unroll
                for (int st = 128; st; st >>= 1)
                    if (sthr[tb + b + st - 1] <= s) b += st;
                unsigned long long up = (1ULL << 32) | (unsigned)(sm_[c] - 1 - b);
                atomicAdd(&acc64[c], up);
            }
            __syncwarp();
        }
        v = vn; row = nrow;
    }
    __syncwarp();
    if (lane < qn) {
        unsigned long long ent = myq[lane];
        int   c = (int)(ent >> 32);
        float s = __uint_as_float((unsigned)(ent & 0xffffffffu));
        int b = 0, tb = c * THRSTRIDE;
        #pragma unroll
        for (int st = 128; st; st >>= 1)
            if (sthr[tb + b + st - 1] <= s) b += st;
        unsigned long long up = (1ULL << 32) | (unsigned)(sm_[c] - 1 - b);
        atomicAdd(&acc64[c], up);
    }
    __syncthreads();
    for (int i = tid; i < NC; i += K3_THREADS) {
        unsigned long long vv = acc64[i];
        if (vv) atomicAdd(&g_acc[i], vv);
    }
}

// ---------------- kernel 4: final combine ----------------
__global__ void __launch_bounds__(256) k4(const float* __restrict__ wt, float* __restrict__ out) {
    __shared__ double sd[256];
    int tid = threadIdx.x;

    double s = 0.0;
    for (int i = tid; i < K1B_BLOCKS; i += 256) s += (double)g_ce_part[i];
    for (int i = tid; i < K1A_BLOCKS; i += 256) s -= 0.001 * (double)g_ps_part[i];
    sd[tid] = s; __syncthreads();
    for (int o = 128; o; o >>= 1) { if (tid < o) sd[tid] += sd[tid + o]; __syncthreads(); }
    double ce = sd[0] / (double)NROWS;
    __syncthreads();

    double pw = 0.0, wsum = 0.0;
    for (int c = tid; c < NC; c += 256) {
        int P = g_P[c], m = g_m[c];
        double pauc = 0.0;
        if (P > 0 && m > 0) {
            unsigned long long a = g_acc[c];
            unsigned long long cr = g_corr[c];
            double isum = (double)(unsigned)(a & 0xffffffffULL) - (double)(unsigned)(cr & 0xffffffffULL);
            double icnt = (double)(unsigned)(a >> 32) - (double)(unsigned)(cr >> 32);
            double Nn = (double)(NROWS - P);
            pauc = (isum + (double)g_wm[c] * icnt) / (Nn * (double)P);
        }
        double w = (double)wt[c];
        pw += pauc * w;
        wsum += w;
    }
    sd[tid] = pw; __syncthreads();
    for (int o = 128; o; o >>= 1) { if (tid < o) sd[tid] += sd[tid + o]; __syncthreads(); }
    double pwt = sd[0]; __syncthreads();
    sd[tid] = wsum; __syncthreads();
    for (int o = 128; o; o >>= 1) { if (tid < o) sd[tid] += sd[tid + o]; __syncthreads(); }
    double wst = sd[0];

    if (tid == 0) {
        double avg = pwt / (wst * 0.05);
        avg = fmin(fmax(avg, 0.0), 1.0);
        out[0] = (float)(0.5 * ce + 0.5 * (1.0 - avg * avg));
    }
}

// ---------------- launch ----------------
extern "C" void kernel_launch(void* const* d_in, const int* in_sizes, int n_in,
                              void* d_out, int out_size) {
    const float* pred = (const float*)d_in[0];
    const int*   tgt  = (const int*)d_in[1];
    const float* wt   = (const float*)d_in[2];
    float*       out  = (float*)d_out;

    cudaFuncSetAttribute(k3, cudaFuncAttributeMaxDynamicSharedMemorySize, K3_SMEM_BYTES);

    k_init<<<16, 256>>>();
    k1a<<<K1A_BLOCKS, K1A_THREADS>>>(pred, tgt, wt);
    k1b<<<K1B_BLOCKS, K1B_THREADS>>>(tgt, wt);
    k2<<<NC, 1024>>>();
    k3f<<<NROWS / 512, 512>>>(tgt);
    k3<<<K3_BLOCKS, K3_THREADS, K3_SMEM_BYTES>>>(pred);
    k4<<<1, 256>>>(wt, out);
}